// round 13
// baseline (speedup 1.0000x reference)
#include <cuda_runtime.h>
#include <cuda_fp16.h>
#include <math.h>

#define BB 16
#define CC 3
#define HH 384
#define WW 1280
#define HW (HH * WW)
#define EPSF 1e-7f

// HWC fp16 staging: per pixel 4 halves {R,G,B,pad} = 8 bytes, aligned. 62.9 MB.
__device__ __half2 g_hwc[(size_t)BB * HW * 2];

__device__ __forceinline__ unsigned int pack_h2(float a, float b) {
    __half2 h = __floats2half2_rn(a, b);
    return *reinterpret_cast<unsigned int*>(&h);
}

// CHW fp32 -> HWC fp16x4 pack (4 px/thread, float4 I/O).
// Signals PDL dependents immediately: sample blocks may start their
// pack-independent prologue while we stream.
__global__ void __launch_bounds__(256)
pack_hwc_kernel(const float* __restrict__ img) {
    asm volatile("griddepcontrol.launch_dependents;");

    int tid = blockIdx.x * blockDim.x + threadIdx.x;
    int p = tid * 4;
    if (p >= BB * HW) return;

    int b = p / HW;
    int rem = p - b * HW;
    const float* plane = img + (size_t)b * CC * HW;

    float4 r  = __ldcs(reinterpret_cast<const float4*>(plane + rem));
    float4 g  = __ldcs(reinterpret_cast<const float4*>(plane + HW + rem));
    float4 bv = __ldcs(reinterpret_cast<const float4*>(plane + 2 * HW + rem));

    uint4 pk0, pk1;
    pk0.x = pack_h2(r.x, g.x);  pk0.y = pack_h2(bv.x, 0.f);
    pk0.z = pack_h2(r.y, g.y);  pk0.w = pack_h2(bv.y, 0.f);
    pk1.x = pack_h2(r.z, g.z);  pk1.y = pack_h2(bv.z, 0.f);
    pk1.z = pack_h2(r.w, g.w);  pk1.w = pack_h2(bv.w, 0.f);

    uint4* dst = reinterpret_cast<uint4*>(&g_hwc[(size_t)p * 2]);
    dst[0] = pk0;
    dst[1] = pk1;
}

__device__ __forceinline__ void tap_rgb(const uint2* __restrict__ src, int idx,
                                        float wgt, float& vr, float& vg, float& vb) {
    uint2 raw = __ldg(src + idx);
    __half2 rg = *reinterpret_cast<__half2*>(&raw.x);
    __half2 bp = *reinterpret_cast<__half2*>(&raw.y);
    float2 rgf = __half22float2(rg);
    float bf = __low2float(bp);
    vr = fmaf(wgt, rgf.x, vr);
    vg = fmaf(wgt, rgf.y, vg);
    vb = fmaf(wgt, bf, vb);
}

// Bilinear warp-sample, 2 px/thread. Per-block fused transform (one batch per
// block: HW % 512 == 0). All pack-independent work happens BEFORE
// griddepcontrol.wait; only the g_hwc gathers come after.
__global__ void __launch_bounds__(256, 4)
warp_sample_kernel(const float* __restrict__ depth,
                   float* __restrict__ out,
                   const float* __restrict__ pose,
                   const float* __restrict__ intr) {
    __shared__ float sA[9];
    __shared__ float sT[3];

    int tid = blockIdx.x * blockDim.x + threadIdx.x;
    int pix0 = tid * 2;
    int b = pix0 / HW;                     // constant within block
    int rem = pix0 - b * HW;               // even; both pixels on the same row
    int h = rem / WW;
    int w = rem - h * WW;

    if (threadIdx.x == 0) {
        float K[9];
#pragma unroll
        for (int i = 0; i < 9; i++) K[i] = intr[b * 9 + i];

        float c00 =  (K[4] * K[8] - K[5] * K[7]);
        float c01 = -(K[3] * K[8] - K[5] * K[6]);
        float c02 =  (K[3] * K[7] - K[4] * K[6]);
        float det = K[0] * c00 + K[1] * c01 + K[2] * c02;
        float id = 1.0f / det;
        float inv[9];
        inv[0] = c00 * id;
        inv[1] = -(K[1] * K[8] - K[2] * K[7]) * id;
        inv[2] =  (K[1] * K[5] - K[2] * K[4]) * id;
        inv[3] = c01 * id;
        inv[4] =  (K[0] * K[8] - K[2] * K[6]) * id;
        inv[5] = -(K[0] * K[5] - K[2] * K[3]) * id;
        inv[6] = c02 * id;
        inv[7] = -(K[0] * K[7] - K[1] * K[6]) * id;
        inv[8] =  (K[0] * K[4] - K[1] * K[3]) * id;

        float ax = pose[b * 6 + 0], ay = pose[b * 6 + 1], az = pose[b * 6 + 2];
        float theta = sqrtf(ax * ax + ay * ay + az * az);
        float ith = 1.0f / (theta + EPSF);
        float x = ax * ith, y = ay * ith, z = az * ith;
        float c = cosf(theta), s = sinf(theta), t = 1.0f - c;
        float R[9];
        R[0] = t * x * x + c;     R[1] = t * x * y - s * z; R[2] = t * z * x + s * y;
        R[3] = t * x * y + s * z; R[4] = t * y * y + c;     R[5] = t * y * z - s * x;
        R[6] = t * z * x - s * y; R[7] = t * y * z + s * x; R[8] = t * z * z + c;

        float KR[9];
#pragma unroll
        for (int i = 0; i < 3; i++)
#pragma unroll
            for (int j = 0; j < 3; j++) {
                float sum = 0.0f;
#pragma unroll
                for (int k = 0; k < 3; k++) sum += K[i * 3 + k] * R[k * 3 + j];
                KR[i * 3 + j] = sum;
            }
#pragma unroll
        for (int i = 0; i < 3; i++)
#pragma unroll
            for (int j = 0; j < 3; j++) {
                float sum = 0.0f;
#pragma unroll
                for (int k = 0; k < 3; k++) sum += KR[i * 3 + k] * inv[k * 3 + j];
                sA[i * 3 + j] = sum;
            }

        float tx = pose[b * 6 + 3], ty = pose[b * 6 + 4], tz = pose[b * 6 + 5];
        sT[0] = K[0] * tx + K[1] * ty + K[2] * tz;
        sT[1] = K[3] * tx + K[4] * ty + K[5] * tz;
        sT[2] = K[6] * tx + K[7] * ty + K[8] * tz;
    }
    __syncthreads();

    float a0 = sA[0], a1 = sA[1], a2 = sA[2];
    float a3 = sA[3], a4 = sA[4], a5 = sA[5];
    float a6 = sA[6], a7 = sA[7], a8 = sA[8];
    float t0 = sT[0], t1 = sT[1], t2 = sT[2];

    float2 d2 = __ldcs(reinterpret_cast<const float2*>(depth + pix0));

    float fy = (float)h;
    float rx = a1 * fy + a2;
    float ry = a4 * fy + a5;
    float rz = a7 * fy + a8;

    // Pack-independent projection for both pixels.
    float xsv[2], ysv[2];
#pragma unroll
    for (int p = 0; p < 2; p++) {
        float fx = (float)(w + p);
        float d  = (p == 0) ? d2.x : d2.y;
        float X = d * (a0 * fx + rx) + t0;
        float Y = d * (a3 * fx + ry) + t1;
        float Z = d * (a6 * fx + rz) + t2 + EPSF;
        float iz = __frcp_rn(Z);
        xsv[p] = X * iz;
        ysv[p] = Y * iz;
    }

    // Everything below consumes pack output.
    asm volatile("griddepcontrol.wait;" ::: "memory");

    const uint2* src = reinterpret_cast<const uint2*>(g_hwc) + (size_t)b * HW;

    float vrA = 0.0f, vgA = 0.0f, vbA = 0.0f;
    float vrB = 0.0f, vgB = 0.0f, vbB = 0.0f;

#pragma unroll
    for (int p = 0; p < 2; p++) {
        float xs = xsv[p], ys = ysv[p];

        float x0f = floorf(xs), y0f = floorf(ys);
        float wx1 = xs - x0f, wx0 = 1.0f - wx1;
        float wy1 = ys - y0f, wy0 = 1.0f - wy1;

        // in-bounds masks on UNCLIPPED coords (reference semantics);
        // x1 = x0+1 -> ibx1 = (x0 >= -1) && (x0 <= W-2)
        float ibx0 = (x0f >= 0.0f  && x0f <= (float)(WW - 1)) ? 1.0f : 0.0f;
        float ibx1 = (x0f >= -1.0f && x0f <= (float)(WW - 2)) ? 1.0f : 0.0f;
        float iby0 = (y0f >= 0.0f  && y0f <= (float)(HH - 1)) ? 1.0f : 0.0f;
        float iby1 = (y0f >= -1.0f && y0f <= (float)(HH - 2)) ? 1.0f : 0.0f;

        int xc0 = (int)fminf(fmaxf(x0f,        0.0f), (float)(WW - 1));
        int xc1 = (int)fminf(fmaxf(x0f + 1.0f, 0.0f), (float)(WW - 1));
        int yc0 = (int)fminf(fmaxf(y0f,        0.0f), (float)(HH - 1));
        int yc1 = (int)fminf(fmaxf(y0f + 1.0f, 0.0f), (float)(HH - 1));

        float w00 = wx0 * wy0 * ibx0 * iby0;
        float w10 = wx1 * wy0 * ibx1 * iby0;
        float w01 = wx0 * wy1 * ibx0 * iby1;
        float w11 = wx1 * wy1 * ibx1 * iby1;

        int r0 = yc0 * WW;
        int r1 = yc1 * WW;

        float vr = 0.0f, vg = 0.0f, vb = 0.0f;
        tap_rgb(src, r0 + xc0, w00, vr, vg, vb);
        tap_rgb(src, r0 + xc1, w10, vr, vg, vb);
        tap_rgb(src, r1 + xc0, w01, vr, vg, vb);
        tap_rgb(src, r1 + xc1, w11, vr, vg, vb);

        if (p == 0) { vrA = vr; vgA = vg; vbA = vb; }
        else        { vrB = vr; vgB = vg; vbB = vb; }
    }

    size_t base = (size_t)b * CC * HW + rem;
    __stcs(reinterpret_cast<float2*>(out + base),          make_float2(vrA, vrB));
    __stcs(reinterpret_cast<float2*>(out + base + HW),     make_float2(vgA, vgB));
    __stcs(reinterpret_cast<float2*>(out + base + 2 * HW), make_float2(vbA, vbB));
}

extern "C" void kernel_launch(void* const* d_in, const int* in_sizes, int n_in,
                              void* d_out, int out_size) {
    const float* source_image = (const float*)d_in[0];
    const float* depth_map    = (const float*)d_in[1];
    const float* pose         = (const float*)d_in[2];
    const float* intrinsic    = (const float*)d_in[3];
    float* out = (float*)d_out;

    const unsigned threads = 256;
    const unsigned pack_blocks   = (BB * HW / 4) / threads;  // 7680
    const unsigned sample_blocks = (BB * HW / 2) / threads;  // 15360

    pack_hwc_kernel<<<pack_blocks, threads>>>(source_image);

    // PDL: sample may begin (prologue) while pack drains; griddepcontrol.wait
    // inside the kernel gates the gathers on pack completion.
    cudaLaunchConfig_t cfg = {};
    cfg.gridDim  = dim3(sample_blocks, 1, 1);
    cfg.blockDim = dim3(threads, 1, 1);
    cfg.dynamicSmemBytes = 0;
    cfg.stream = 0;
    cudaLaunchAttribute attrs[1];
    attrs[0].id = cudaLaunchAttributeProgrammaticStreamSerialization;
    attrs[0].val.programmaticStreamSerializationAllowed = 1;
    cfg.attrs = attrs;
    cfg.numAttrs = 1;
    cudaLaunchKernelEx(&cfg, warp_sample_kernel, depth_map, out,
                       (const float*)pose, (const float*)intrinsic);
}

// round 14
// speedup vs baseline: 1.1749x; 1.1749x over previous
#include <cuda_runtime.h>
#include <cuda_fp16.h>
#include <math.h>

#define BB 16
#define CC 3
#define HH 384
#define WW 1280
#define HW (HH * WW)
#define EPSF 1e-7f

// Per-batch fused transform: coord = d * A @ [x,y,1] + tv   (A = K R K^-1, tv = K t)
__device__ float g_A[BB][9];
__device__ float g_tv[BB][3];

// HWC fp16 staging: per pixel 4 halves {R,G,B,pad} = 8 bytes, aligned. 62.9 MB.
__device__ __half2 g_hwc[(size_t)BB * HW * 2];

__device__ __forceinline__ unsigned int pack_h2(float a, float b) {
    __half2 h = __floats2half2_rn(a, b);
    return *reinterpret_cast<unsigned int*>(&h);
}

__device__ __forceinline__ void compute_mats_one(const float* __restrict__ pose,
                                                 const float* __restrict__ intr,
                                                 int b) {
    float K[9];
#pragma unroll
    for (int i = 0; i < 9; i++) K[i] = intr[b * 9 + i];

    float c00 =  (K[4] * K[8] - K[5] * K[7]);
    float c01 = -(K[3] * K[8] - K[5] * K[6]);
    float c02 =  (K[3] * K[7] - K[4] * K[6]);
    float det = K[0] * c00 + K[1] * c01 + K[2] * c02;
    float id = 1.0f / det;
    float inv[9];
    inv[0] = c00 * id;
    inv[1] = -(K[1] * K[8] - K[2] * K[7]) * id;
    inv[2] =  (K[1] * K[5] - K[2] * K[4]) * id;
    inv[3] = c01 * id;
    inv[4] =  (K[0] * K[8] - K[2] * K[6]) * id;
    inv[5] = -(K[0] * K[5] - K[2] * K[3]) * id;
    inv[6] = c02 * id;
    inv[7] = -(K[0] * K[7] - K[1] * K[6]) * id;
    inv[8] =  (K[0] * K[4] - K[1] * K[3]) * id;

    float ax = pose[b * 6 + 0], ay = pose[b * 6 + 1], az = pose[b * 6 + 2];
    float theta = sqrtf(ax * ax + ay * ay + az * az);
    float ith = 1.0f / (theta + EPSF);
    float x = ax * ith, y = ay * ith, z = az * ith;
    float c = cosf(theta), s = sinf(theta), t = 1.0f - c;
    float R[9];
    R[0] = t * x * x + c;     R[1] = t * x * y - s * z; R[2] = t * z * x + s * y;
    R[3] = t * x * y + s * z; R[4] = t * y * y + c;     R[5] = t * y * z - s * x;
    R[6] = t * z * x - s * y; R[7] = t * y * z + s * x; R[8] = t * z * z + c;

    float KR[9];
#pragma unroll
    for (int i = 0; i < 3; i++)
#pragma unroll
        for (int j = 0; j < 3; j++) {
            float sum = 0.0f;
#pragma unroll
            for (int k = 0; k < 3; k++) sum += K[i * 3 + k] * R[k * 3 + j];
            KR[i * 3 + j] = sum;
        }
#pragma unroll
    for (int i = 0; i < 3; i++)
#pragma unroll
        for (int j = 0; j < 3; j++) {
            float sum = 0.0f;
#pragma unroll
            for (int k = 0; k < 3; k++) sum += KR[i * 3 + k] * inv[k * 3 + j];
            g_A[b][i * 3 + j] = sum;
        }

    float tx = pose[b * 6 + 3], ty = pose[b * 6 + 4], tz = pose[b * 6 + 5];
    g_tv[b][0] = K[0] * tx + K[1] * ty + K[2] * tz;
    g_tv[b][1] = K[3] * tx + K[4] * ty + K[5] * tz;
    g_tv[b][2] = K[6] * tx + K[7] * ty + K[8] * tz;
}

// CHW fp32 -> HWC fp16x4 pack (4 px/thread, float4 I/O) + fused mat precompute.
// launch_dependents at entry: sample grid may start launching while we stream;
// its griddepcontrol.wait guarantees visibility of ALL our stores.
__global__ void __launch_bounds__(256)
pack_hwc_kernel(const float* __restrict__ img,
                const float* __restrict__ pose,
                const float* __restrict__ intr) {
    asm volatile("griddepcontrol.launch_dependents;");

    if (blockIdx.x == 0 && threadIdx.x < BB) {
        compute_mats_one(pose, intr, threadIdx.x);
    }

    int tid = blockIdx.x * blockDim.x + threadIdx.x;
    int p = tid * 4;
    if (p >= BB * HW) return;

    int b = p / HW;
    int rem = p - b * HW;
    const float* plane = img + (size_t)b * CC * HW;

    float4 r  = __ldcs(reinterpret_cast<const float4*>(plane + rem));
    float4 g  = __ldcs(reinterpret_cast<const float4*>(plane + HW + rem));
    float4 bv = __ldcs(reinterpret_cast<const float4*>(plane + 2 * HW + rem));

    uint4 pk0, pk1;
    pk0.x = pack_h2(r.x, g.x);  pk0.y = pack_h2(bv.x, 0.f);
    pk0.z = pack_h2(r.y, g.y);  pk0.w = pack_h2(bv.y, 0.f);
    pk1.x = pack_h2(r.z, g.z);  pk1.y = pack_h2(bv.z, 0.f);
    pk1.z = pack_h2(r.w, g.w);  pk1.w = pack_h2(bv.w, 0.f);

    uint4* dst = reinterpret_cast<uint4*>(&g_hwc[(size_t)p * 2]);
    dst[0] = pk0;
    dst[1] = pk1;
}

__device__ __forceinline__ void tap_rgb(const uint2* __restrict__ src, int idx,
                                        float wgt, float& vr, float& vg, float& vb) {
    uint2 raw = __ldg(src + idx);
    __half2 rg = *reinterpret_cast<__half2*>(&raw.x);
    __half2 bp = *reinterpret_cast<__half2*>(&raw.y);
    float2 rgf = __half22float2(rg);
    float bf = __low2float(bp);
    vr = fmaf(wgt, rgf.x, vr);
    vg = fmaf(wgt, rgf.y, vg);
    vb = fmaf(wgt, bf, vb);
}

// Bilinear warp-sample, 2 px/thread — EXACT R12 body; only the depth load is
// hoisted above griddepcontrol.wait (depth doesn't depend on pack).
__global__ void __launch_bounds__(256, 4)
warp_sample_kernel(const float* __restrict__ depth,
                   float* __restrict__ out) {
    int tid = blockIdx.x * blockDim.x + threadIdx.x;
    int pix0 = tid * 2;
    if (pix0 >= BB * HW) return;

    int b = pix0 / HW;
    int rem = pix0 - b * HW;               // even; both pixels on the same row
    int h = rem / WW;
    int w = rem - h * WW;

    // pack-independent: issue early, overlaps pack tail.
    float2 d2 = __ldcs(reinterpret_cast<const float2*>(depth + pix0));

    // gate everything that reads pack output (g_A, g_tv, g_hwc).
    asm volatile("griddepcontrol.wait;" ::: "memory");

    float a0 = g_A[b][0], a1 = g_A[b][1], a2 = g_A[b][2];
    float a3 = g_A[b][3], a4 = g_A[b][4], a5 = g_A[b][5];
    float a6 = g_A[b][6], a7 = g_A[b][7], a8 = g_A[b][8];
    float t0 = g_tv[b][0], t1 = g_tv[b][1], t2 = g_tv[b][2];

    float fy = (float)h;
    float rx = a1 * fy + a2;
    float ry = a4 * fy + a5;
    float rz = a7 * fy + a8;

    const uint2* src = reinterpret_cast<const uint2*>(g_hwc) + (size_t)b * HW;

    float vrA = 0.0f, vgA = 0.0f, vbA = 0.0f;
    float vrB = 0.0f, vgB = 0.0f, vbB = 0.0f;

#pragma unroll
    for (int p = 0; p < 2; p++) {
        float fx = (float)(w + p);
        float d  = (p == 0) ? d2.x : d2.y;
        float X = d * (a0 * fx + rx) + t0;
        float Y = d * (a3 * fx + ry) + t1;
        float Z = d * (a6 * fx + rz) + t2 + EPSF;

        float iz = __frcp_rn(Z);           // one reciprocal instead of two divides
        float xs = X * iz;
        float ys = Y * iz;

        float x0f = floorf(xs), y0f = floorf(ys);
        float wx1 = xs - x0f, wx0 = 1.0f - wx1;
        float wy1 = ys - y0f, wy0 = 1.0f - wy1;

        // in-bounds masks on UNCLIPPED coords (reference semantics);
        // x1 = x0+1 -> ibx1 = (x0 >= -1) && (x0 <= W-2)
        float ibx0 = (x0f >= 0.0f  && x0f <= (float)(WW - 1)) ? 1.0f : 0.0f;
        float ibx1 = (x0f >= -1.0f && x0f <= (float)(WW - 2)) ? 1.0f : 0.0f;
        float iby0 = (y0f >= 0.0f  && y0f <= (float)(HH - 1)) ? 1.0f : 0.0f;
        float iby1 = (y0f >= -1.0f && y0f <= (float)(HH - 2)) ? 1.0f : 0.0f;

        int xc0 = (int)fminf(fmaxf(x0f,        0.0f), (float)(WW - 1));
        int xc1 = (int)fminf(fmaxf(x0f + 1.0f, 0.0f), (float)(WW - 1));
        int yc0 = (int)fminf(fmaxf(y0f,        0.0f), (float)(HH - 1));
        int yc1 = (int)fminf(fmaxf(y0f + 1.0f, 0.0f), (float)(HH - 1));

        float w00 = wx0 * wy0 * ibx0 * iby0;
        float w10 = wx1 * wy0 * ibx1 * iby0;
        float w01 = wx0 * wy1 * ibx0 * iby1;
        float w11 = wx1 * wy1 * ibx1 * iby1;

        int r0 = yc0 * WW;
        int r1 = yc1 * WW;

        float vr = 0.0f, vg = 0.0f, vb = 0.0f;
        tap_rgb(src, r0 + xc0, w00, vr, vg, vb);
        tap_rgb(src, r0 + xc1, w10, vr, vg, vb);
        tap_rgb(src, r1 + xc0, w01, vr, vg, vb);
        tap_rgb(src, r1 + xc1, w11, vr, vg, vb);

        if (p == 0) { vrA = vr; vgA = vg; vbA = vb; }
        else        { vrB = vr; vgB = vg; vbB = vb; }
    }

    size_t base = (size_t)b * CC * HW + rem;
    __stcs(reinterpret_cast<float2*>(out + base),          make_float2(vrA, vrB));
    __stcs(reinterpret_cast<float2*>(out + base + HW),     make_float2(vgA, vgB));
    __stcs(reinterpret_cast<float2*>(out + base + 2 * HW), make_float2(vbA, vbB));
}

extern "C" void kernel_launch(void* const* d_in, const int* in_sizes, int n_in,
                              void* d_out, int out_size) {
    const float* source_image = (const float*)d_in[0];
    const float* depth_map    = (const float*)d_in[1];
    const float* pose         = (const float*)d_in[2];
    const float* intrinsic    = (const float*)d_in[3];
    float* out = (float*)d_out;

    const unsigned threads = 256;
    const unsigned pack_blocks   = (BB * HW / 4) / threads;  // 7680
    const unsigned sample_blocks = (BB * HW / 2) / threads;  // 15360

    pack_hwc_kernel<<<pack_blocks, threads>>>(source_image, pose, intrinsic);

    cudaLaunchConfig_t cfg = {};
    cfg.gridDim  = dim3(sample_blocks, 1, 1);
    cfg.blockDim = dim3(threads, 1, 1);
    cfg.dynamicSmemBytes = 0;
    cfg.stream = 0;
    cudaLaunchAttribute attrs[1];
    attrs[0].id = cudaLaunchAttributeProgrammaticStreamSerialization;
    attrs[0].val.programmaticStreamSerializationAllowed = 1;
    cfg.attrs = attrs;
    cfg.numAttrs = 1;
    cudaLaunchKernelEx(&cfg, warp_sample_kernel, depth_map, out);
}

// round 15
// speedup vs baseline: 1.1915x; 1.0141x over previous
#include <cuda_runtime.h>
#include <cuda_fp16.h>
#include <math.h>

#define BB 16
#define CC 3
#define HH 384
#define WW 1280
#define HW (HH * WW)
#define EPSF 1e-7f

// Per-batch fused transform: coord = d * A @ [x,y,1] + tv   (A = K R K^-1, tv = K t)
__device__ float g_A[BB][9];
__device__ float g_tv[BB][3];

// HWC fp16 staging: per pixel 4 halves {R,G,B,pad} = 8 bytes, aligned. 62.9 MB.
__device__ __half2 g_hwc[(size_t)BB * HW * 2];

__device__ __forceinline__ unsigned int pack_h2(float a, float b) {
    __half2 h = __floats2half2_rn(a, b);
    return *reinterpret_cast<unsigned int*>(&h);
}

__device__ __forceinline__ void compute_mats_one(const float* __restrict__ pose,
                                                 const float* __restrict__ intr,
                                                 int b) {
    float K[9];
#pragma unroll
    for (int i = 0; i < 9; i++) K[i] = intr[b * 9 + i];

    float c00 =  (K[4] * K[8] - K[5] * K[7]);
    float c01 = -(K[3] * K[8] - K[5] * K[6]);
    float c02 =  (K[3] * K[7] - K[4] * K[6]);
    float det = K[0] * c00 + K[1] * c01 + K[2] * c02;
    float id = 1.0f / det;
    float inv[9];
    inv[0] = c00 * id;
    inv[1] = -(K[1] * K[8] - K[2] * K[7]) * id;
    inv[2] =  (K[1] * K[5] - K[2] * K[4]) * id;
    inv[3] = c01 * id;
    inv[4] =  (K[0] * K[8] - K[2] * K[6]) * id;
    inv[5] = -(K[0] * K[5] - K[2] * K[3]) * id;
    inv[6] = c02 * id;
    inv[7] = -(K[0] * K[7] - K[1] * K[6]) * id;
    inv[8] =  (K[0] * K[4] - K[1] * K[3]) * id;

    float ax = pose[b * 6 + 0], ay = pose[b * 6 + 1], az = pose[b * 6 + 2];
    float theta = sqrtf(ax * ax + ay * ay + az * az);
    float ith = 1.0f / (theta + EPSF);
    float x = ax * ith, y = ay * ith, z = az * ith;
    float c = cosf(theta), s = sinf(theta), t = 1.0f - c;
    float R[9];
    R[0] = t * x * x + c;     R[1] = t * x * y - s * z; R[2] = t * z * x + s * y;
    R[3] = t * x * y + s * z; R[4] = t * y * y + c;     R[5] = t * y * z - s * x;
    R[6] = t * z * x - s * y; R[7] = t * y * z + s * x; R[8] = t * z * z + c;

    float KR[9];
#pragma unroll
    for (int i = 0; i < 3; i++)
#pragma unroll
        for (int j = 0; j < 3; j++) {
            float sum = 0.0f;
#pragma unroll
            for (int k = 0; k < 3; k++) sum += K[i * 3 + k] * R[k * 3 + j];
            KR[i * 3 + j] = sum;
        }
#pragma unroll
    for (int i = 0; i < 3; i++)
#pragma unroll
        for (int j = 0; j < 3; j++) {
            float sum = 0.0f;
#pragma unroll
            for (int k = 0; k < 3; k++) sum += KR[i * 3 + k] * inv[k * 3 + j];
            g_A[b][i * 3 + j] = sum;
        }

    float tx = pose[b * 6 + 3], ty = pose[b * 6 + 4], tz = pose[b * 6 + 5];
    g_tv[b][0] = K[0] * tx + K[1] * ty + K[2] * tz;
    g_tv[b][1] = K[3] * tx + K[4] * ty + K[5] * tz;
    g_tv[b][2] = K[6] * tx + K[7] * ty + K[8] * tz;
}

// CHW fp32 -> HWC fp16x4 pack (4 px/thread, float4 I/O) + fused mat precompute.
// Grid exactly tiles BB*HW/4 threads -> no bounds guard needed.
__global__ void __launch_bounds__(256)
pack_hwc_kernel(const float* __restrict__ img,
                const float* __restrict__ pose,
                const float* __restrict__ intr) {
    asm volatile("griddepcontrol.launch_dependents;");

    if (blockIdx.x == 0 && threadIdx.x < BB) {
        compute_mats_one(pose, intr, threadIdx.x);
    }

    int tid = blockIdx.x * blockDim.x + threadIdx.x;
    int p = tid * 4;

    int b = p / HW;
    int rem = p - b * HW;
    const float* plane = img + (size_t)b * CC * HW;

    float4 r  = __ldcs(reinterpret_cast<const float4*>(plane + rem));
    float4 g  = __ldcs(reinterpret_cast<const float4*>(plane + HW + rem));
    float4 bv = __ldcs(reinterpret_cast<const float4*>(plane + 2 * HW + rem));

    uint4 pk0, pk1;
    pk0.x = pack_h2(r.x, g.x);  pk0.y = pack_h2(bv.x, 0.f);
    pk0.z = pack_h2(r.y, g.y);  pk0.w = pack_h2(bv.y, 0.f);
    pk1.x = pack_h2(r.z, g.z);  pk1.y = pack_h2(bv.z, 0.f);
    pk1.z = pack_h2(r.w, g.w);  pk1.w = pack_h2(bv.w, 0.f);

    uint4* dst = reinterpret_cast<uint4*>(&g_hwc[(size_t)p * 2]);
    dst[0] = pk0;
    dst[1] = pk1;
}

__device__ __forceinline__ void tap_rgb(const uint2* __restrict__ src, int idx,
                                        float wgt, float& vr, float& vg, float& vb) {
    uint2 raw = __ldg(src + idx);
    __half2 rg = *reinterpret_cast<__half2*>(&raw.x);
    __half2 bp = *reinterpret_cast<__half2*>(&raw.y);
    float2 rgf = __half22float2(rg);
    float bf = __low2float(bp);
    vr = fmaf(wgt, rgf.x, vr);
    vg = fmaf(wgt, rgf.y, vg);
    vb = fmaf(wgt, bf, vb);
}

// Bilinear warp-sample, 2 px/thread. Grid exactly tiles BB*HW/2 threads.
// Depth load hoisted above griddepcontrol.wait (pack-independent).
__global__ void __launch_bounds__(256, 4)
warp_sample_kernel(const float* __restrict__ depth,
                   float* __restrict__ out) {
    int tid = blockIdx.x * blockDim.x + threadIdx.x;
    int pix0 = tid * 2;

    int b = pix0 / HW;
    int rem = pix0 - b * HW;               // even; both pixels on the same row
    int h = rem / WW;
    int w = rem - h * WW;

    // pack-independent: issue early, overlaps pack tail.
    float2 d2 = __ldcs(reinterpret_cast<const float2*>(depth + pix0));

    // gate everything that reads pack output (g_A, g_tv, g_hwc).
    asm volatile("griddepcontrol.wait;" ::: "memory");

    float a0 = g_A[b][0], a1 = g_A[b][1], a2 = g_A[b][2];
    float a3 = g_A[b][3], a4 = g_A[b][4], a5 = g_A[b][5];
    float a6 = g_A[b][6], a7 = g_A[b][7], a8 = g_A[b][8];
    float t0 = g_tv[b][0], t1 = g_tv[b][1], t2 = g_tv[b][2];

    float fy = (float)h;
    float rx = a1 * fy + a2;
    float ry = a4 * fy + a5;
    float rz = a7 * fy + a8;

    const uint2* src = reinterpret_cast<const uint2*>(g_hwc) + (size_t)b * HW;

    float vrA = 0.0f, vgA = 0.0f, vbA = 0.0f;
    float vrB = 0.0f, vgB = 0.0f, vbB = 0.0f;

#pragma unroll
    for (int p = 0; p < 2; p++) {
        float fx = (float)(w + p);
        float d  = (p == 0) ? d2.x : d2.y;
        float X = d * (a0 * fx + rx) + t0;
        float Y = d * (a3 * fx + ry) + t1;
        float Z = d * (a6 * fx + rz) + t2 + EPSF;

        float iz = __frcp_rn(Z);           // one reciprocal instead of two divides
        float xs = X * iz;
        float ys = Y * iz;

        float x0f = floorf(xs), y0f = floorf(ys);
        float wx1 = xs - x0f, wx0 = 1.0f - wx1;
        float wy1 = ys - y0f, wy0 = 1.0f - wy1;

        // in-bounds masks on UNCLIPPED coords (reference semantics);
        // x1 = x0+1 -> ibx1 = (x0 >= -1) && (x0 <= W-2)
        float ibx0 = (x0f >= 0.0f  && x0f <= (float)(WW - 1)) ? 1.0f : 0.0f;
        float ibx1 = (x0f >= -1.0f && x0f <= (float)(WW - 2)) ? 1.0f : 0.0f;
        float iby0 = (y0f >= 0.0f  && y0f <= (float)(HH - 1)) ? 1.0f : 0.0f;
        float iby1 = (y0f >= -1.0f && y0f <= (float)(HH - 2)) ? 1.0f : 0.0f;

        int xc0 = (int)fminf(fmaxf(x0f,        0.0f), (float)(WW - 1));
        int xc1 = (int)fminf(fmaxf(x0f + 1.0f, 0.0f), (float)(WW - 1));
        int yc0 = (int)fminf(fmaxf(y0f,        0.0f), (float)(HH - 1));
        int yc1 = (int)fminf(fmaxf(y0f + 1.0f, 0.0f), (float)(HH - 1));

        float w00 = wx0 * wy0 * ibx0 * iby0;
        float w10 = wx1 * wy0 * ibx1 * iby0;
        float w01 = wx0 * wy1 * ibx0 * iby1;
        float w11 = wx1 * wy1 * ibx1 * iby1;

        int r0 = yc0 * WW;
        int r1 = yc1 * WW;

        float vr = 0.0f, vg = 0.0f, vb = 0.0f;
        tap_rgb(src, r0 + xc0, w00, vr, vg, vb);
        tap_rgb(src, r0 + xc1, w10, vr, vg, vb);
        tap_rgb(src, r1 + xc0, w01, vr, vg, vb);
        tap_rgb(src, r1 + xc1, w11, vr, vg, vb);

        if (p == 0) { vrA = vr; vgA = vg; vbA = vb; }
        else        { vrB = vr; vgB = vg; vbB = vb; }
    }

    size_t base = (size_t)b * CC * HW + rem;
    __stcs(reinterpret_cast<float2*>(out + base),          make_float2(vrA, vrB));
    __stcs(reinterpret_cast<float2*>(out + base + HW),     make_float2(vgA, vgB));
    __stcs(reinterpret_cast<float2*>(out + base + 2 * HW), make_float2(vbA, vbB));
}

extern "C" void kernel_launch(void* const* d_in, const int* in_sizes, int n_in,
                              void* d_out, int out_size) {
    const float* source_image = (const float*)d_in[0];
    const float* depth_map    = (const float*)d_in[1];
    const float* pose         = (const float*)d_in[2];
    const float* intrinsic    = (const float*)d_in[3];
    float* out = (float*)d_out;

    const unsigned threads = 256;
    const unsigned pack_blocks   = (BB * HW / 4) / threads;  // 7680, exact tiling
    const unsigned sample_blocks = (BB * HW / 2) / threads;  // 15360, exact tiling

    pack_hwc_kernel<<<pack_blocks, threads>>>(source_image, pose, intrinsic);

    cudaLaunchConfig_t cfg = {};
    cfg.gridDim  = dim3(sample_blocks, 1, 1);
    cfg.blockDim = dim3(threads, 1, 1);
    cfg.dynamicSmemBytes = 0;
    cfg.stream = 0;
    cudaLaunchAttribute attrs[1];
    attrs[0].id = cudaLaunchAttributeProgrammaticStreamSerialization;
    attrs[0].val.programmaticStreamSerializationAllowed = 1;
    cfg.attrs = attrs;
    cfg.numAttrs = 1;
    cudaLaunchKernelEx(&cfg, warp_sample_kernel, depth_map, out);
}